// round 1
// baseline (speedup 1.0000x reference)
#include <cuda_runtime.h>
#include <mma.h>
#include <math.h>

using namespace nvcuda;

#define T_TOK 4096
#define DM    1024
#define DFF   4096
#define NE    8

// Scratch (static device memory — allowed; no runtime allocation)
__device__ int   g_count[NE];
__device__ int   g_off[NE];
__device__ int   g_tok[NE * T_TOK];
__device__ float g_gate[NE * T_TOK];
__device__ float g_H[(size_t)2 * T_TOK * DFF];   // 8192 x 4096 fp32 = 134MB

// ---------------------------------------------------------------------------
// Init: zero output accumulator and per-expert counters
// ---------------------------------------------------------------------------
__global__ void init_kernel(float* __restrict__ out, int out_size) {
    int i = blockIdx.x * blockDim.x + threadIdx.x;
    int stride = gridDim.x * blockDim.x;
    for (int j = i; j < out_size; j += stride) out[j] = 0.0f;
    if (blockIdx.x == 0 && threadIdx.x < NE) g_count[threadIdx.x] = 0;
}

// ---------------------------------------------------------------------------
// Router: warp per token, fp32 exact logits, top-2 + softmax, append to lists
// ---------------------------------------------------------------------------
__global__ void router_kernel(const float* __restrict__ x,
                              const float* __restrict__ rw,
                              const float* __restrict__ rb) {
    __shared__ float s_rw[DM * NE];  // 32KB
    int tid = threadIdx.x;
    for (int i = tid; i < DM * NE; i += blockDim.x) s_rw[i] = rw[i];
    __syncthreads();

    int warp = tid >> 5, lane = tid & 31;
    int t = blockIdx.x * 8 + warp;     // grid = 512 blocks x 8 warps = 4096
    if (t >= T_TOK) return;

    float acc[NE];
#pragma unroll
    for (int e = 0; e < NE; e++) acc[e] = 0.0f;

    const float* xr = x + (size_t)t * DM;
    for (int d = lane; d < DM; d += 32) {
        float xv = xr[d];
#pragma unroll
        for (int e = 0; e < NE; e++) acc[e] += xv * s_rw[d * NE + e];
    }
#pragma unroll
    for (int e = 0; e < NE; e++) {
#pragma unroll
        for (int o = 16; o > 0; o >>= 1)
            acc[e] += __shfl_xor_sync(0xffffffff, acc[e], o);
    }

    if (lane == 0) {
        float l[NE];
#pragma unroll
        for (int e = 0; e < NE; e++) l[e] = acc[e] + rb[e];
        // top-2 (strictly-greater => lowest index wins on ties, matching top_k)
        int i0 = 0;
#pragma unroll
        for (int e = 1; e < NE; e++) if (l[e] > l[i0]) i0 = e;
        int i1 = (i0 == 0) ? 1 : 0;
#pragma unroll
        for (int e = 0; e < NE; e++) if (e != i0 && l[e] > l[i1]) i1 = e;

        float m  = l[i0];
        float e1 = expf(l[i1] - m);
        float s  = 1.0f + e1;
        float g0 = 1.0f / s;
        float g1 = e1 / s;

        int p0 = atomicAdd(&g_count[i0], 1);
        g_tok[i0 * T_TOK + p0]  = t;
        g_gate[i0 * T_TOK + p0] = g0;
        int p1 = atomicAdd(&g_count[i1], 1);
        g_tok[i1 * T_TOK + p1]  = t;
        g_gate[i1 * T_TOK + p1] = g1;
    }
}

// ---------------------------------------------------------------------------
// Prefix offsets over 8 experts
// ---------------------------------------------------------------------------
__global__ void prefix_kernel() {
    if (threadIdx.x == 0) {
        int s = 0;
#pragma unroll
        for (int e = 0; e < NE; e++) { g_off[e] = s; s += g_count[e]; }
    }
}

// ---------------------------------------------------------------------------
// Grouped GEMM, tf32 WMMA, tile 128x64, BK=16.
// MODE 0: H[row] = gelu(x[tok] @ w1[e] + b1[e])      (N=DFF, K=DM)
// MODE 1: out[tok] += gate * (H[row] @ w2[e] + b2[e]) (N=DM,  K=DFF)
// ---------------------------------------------------------------------------
template <int MODE>
__global__ void moe_gemm(const float* __restrict__ x,
                         const float* __restrict__ W,
                         const float* __restrict__ bias,
                         float* __restrict__ out) {
    constexpr int N  = (MODE == 0) ? DFF : DM;
    constexpr int KD = (MODE == 0) ? DM  : DFF;

    const int e   = blockIdx.z;
    const int cnt = g_count[e];
    const int rowBase = blockIdx.y * 128;
    if (rowBase >= cnt) return;
    const int colBase = blockIdx.x * 64;
    const int off = g_off[e];

    __shared__ float sm[8192];        // 32KB: A(2048) + B(1024) in mainloop, C(8192) in epilogue
    float* sA = sm;                   // 128 x 16
    float* sB = sm + 2048;            // 16 x 64

    const int tid  = threadIdx.x;
    const int warp = tid >> 5;
    const int wm = warp >> 1, wn = warp & 1;   // 4x2 warp grid, 32x32 per warp

    wmma::fragment<wmma::accumulator, 16, 16, 8, float> c[2][2];
#pragma unroll
    for (int i = 0; i < 2; i++)
#pragma unroll
        for (int j = 0; j < 2; j++) wmma::fill_fragment(c[i][j], 0.0f);

    const float* Wbase = W + (size_t)e * KD * N;
    const float* Abase = (MODE == 0) ? x : g_H;

    for (int kt = 0; kt < KD; kt += 16) {
        // ---- load A tile (128x16), gathered rows, zero-fill past cnt ----
#pragma unroll
        for (int i = 0; i < 2; i++) {
            int f   = tid + i * 256;
            int row = f >> 2;
            int c4  = (f & 3) * 4;
            int gr  = rowBase + row;
            float4 v = make_float4(0.f, 0.f, 0.f, 0.f);
            if (gr < cnt) {
                size_t arow;
                if (MODE == 0) arow = (size_t)g_tok[e * T_TOK + gr] * DM;
                else           arow = (size_t)(off + gr) * DFF;
                v = *(const float4*)(Abase + arow + kt + c4);
            }
            *(float4*)(sA + row * 16 + c4) = v;
        }
        // ---- load B tile (16x64) ----
        {
            int k  = tid >> 4;
            int n4 = (tid & 15) * 4;
            *(float4*)(sB + k * 64 + n4) =
                *(const float4*)(Wbase + (size_t)(kt + k) * N + colBase + n4);
        }
        __syncthreads();

#pragma unroll
        for (int ks = 0; ks < 16; ks += 8) {
            wmma::fragment<wmma::matrix_a, 16, 16, 8, wmma::precision::tf32, wmma::row_major> a[2];
            wmma::fragment<wmma::matrix_b, 16, 16, 8, wmma::precision::tf32, wmma::row_major> b[2];
#pragma unroll
            for (int i = 0; i < 2; i++) {
                wmma::load_matrix_sync(a[i], sA + (wm * 32 + i * 16) * 16 + ks, 16);
#pragma unroll
                for (int t2 = 0; t2 < a[i].num_elements; t2++)
                    a[i].x[t2] = wmma::__float_to_tf32(a[i].x[t2]);
                wmma::load_matrix_sync(b[i], sB + ks * 64 + wn * 32 + i * 16, 64);
#pragma unroll
                for (int t2 = 0; t2 < b[i].num_elements; t2++)
                    b[i].x[t2] = wmma::__float_to_tf32(b[i].x[t2]);
            }
#pragma unroll
            for (int i = 0; i < 2; i++)
#pragma unroll
                for (int j = 0; j < 2; j++)
                    wmma::mma_sync(c[i][j], a[i], b[j], c[i][j]);
        }
        __syncthreads();
    }

    // ---- epilogue: stage C in shared (reuses A/B space), then transform ----
    float* sC = sm;
#pragma unroll
    for (int i = 0; i < 2; i++)
#pragma unroll
        for (int j = 0; j < 2; j++)
            wmma::store_matrix_sync(sC + (wm * 32 + i * 16) * 64 + wn * 32 + j * 16,
                                    c[i][j], 64, wmma::mem_row_major);
    __syncthreads();

#pragma unroll 8
    for (int i = 0; i < 32; i++) {
        int idx = i * 256 + tid;
        int row = idx >> 6, col = idx & 63;
        int gr  = rowBase + row;
        if (gr < cnt) {
            float v = sC[idx] + bias[e * N + colBase + col];
            if (MODE == 0) {
                float g = 0.5f * v * (1.0f + erff(v * 0.70710678118654752f));
                g_H[(size_t)(off + gr) * DFF + colBase + col] = g;
            } else {
                int   tok  = g_tok[e * T_TOK + gr];
                float gate = g_gate[e * T_TOK + gr];
                atomicAdd(out + (size_t)tok * DM + colBase + col, gate * v);
            }
        }
    }
}

// ---------------------------------------------------------------------------
extern "C" void kernel_launch(void* const* d_in, const int* in_sizes, int n_in,
                              void* d_out, int out_size) {
    const float* x  = (const float*)d_in[0];
    const float* rw = (const float*)d_in[1];
    const float* rb = (const float*)d_in[2];
    const float* w1 = (const float*)d_in[3];
    const float* b1 = (const float*)d_in[4];
    const float* w2 = (const float*)d_in[5];
    const float* b2 = (const float*)d_in[6];
    float* out = (float*)d_out;

    init_kernel<<<1024, 256>>>(out, out_size);
    router_kernel<<<512, 256>>>(x, rw, rb);
    prefix_kernel<<<1, 32>>>();
    moe_gemm<0><<<dim3(DFF / 64, T_TOK / 128, NE), 256>>>(x, w1, b1, nullptr);
    moe_gemm<1><<<dim3(DM  / 64, T_TOK / 128, NE), 256>>>(nullptr, w2, b2, out);
}

// round 2
// speedup vs baseline: 1.5145x; 1.5145x over previous
#include <cuda_runtime.h>
#include <mma.h>
#include <math.h>
#include <stdint.h>

using namespace nvcuda;

#define T_TOK 4096
#define DM    1024
#define DFF   4096
#define NE    8

// Scratch (static device memory — allowed; no runtime allocation)
__device__ int   g_count[NE];
__device__ int   g_off[NE];
__device__ int   g_tok[NE * T_TOK];
__device__ float g_gate[NE * T_TOK];
__device__ float g_H[(size_t)2 * T_TOK * DFF];   // 8192 x 4096 fp32 = 134MB

// ---------------------------------------------------------------------------
// Init: zero output accumulator and per-expert counters
// ---------------------------------------------------------------------------
__global__ void init_kernel(float* __restrict__ out, int out_size) {
    int i = blockIdx.x * blockDim.x + threadIdx.x;
    int stride = gridDim.x * blockDim.x;
    for (int j = i; j < out_size; j += stride) out[j] = 0.0f;
    if (blockIdx.x == 0 && threadIdx.x < NE) g_count[threadIdx.x] = 0;
}

// ---------------------------------------------------------------------------
// Router: warp per token, fp32 exact logits, top-2 + softmax, append to lists
// ---------------------------------------------------------------------------
__global__ void router_kernel(const float* __restrict__ x,
                              const float* __restrict__ rw,
                              const float* __restrict__ rb) {
    __shared__ float s_rw[DM * NE];  // 32KB
    int tid = threadIdx.x;
    for (int i = tid; i < DM * NE; i += blockDim.x) s_rw[i] = rw[i];
    __syncthreads();

    int warp = tid >> 5, lane = tid & 31;
    int t = blockIdx.x * 8 + warp;     // grid = 512 blocks x 8 warps = 4096
    if (t >= T_TOK) return;

    float acc[NE];
#pragma unroll
    for (int e = 0; e < NE; e++) acc[e] = 0.0f;

    const float* xr = x + (size_t)t * DM;
    for (int d = lane; d < DM; d += 32) {
        float xv = xr[d];
#pragma unroll
        for (int e = 0; e < NE; e++) acc[e] += xv * s_rw[d * NE + e];
    }
#pragma unroll
    for (int e = 0; e < NE; e++) {
#pragma unroll
        for (int o = 16; o > 0; o >>= 1)
            acc[e] += __shfl_xor_sync(0xffffffff, acc[e], o);
    }

    if (lane == 0) {
        float l[NE];
#pragma unroll
        for (int e = 0; e < NE; e++) l[e] = acc[e] + rb[e];
        int i0 = 0;
#pragma unroll
        for (int e = 1; e < NE; e++) if (l[e] > l[i0]) i0 = e;
        int i1 = (i0 == 0) ? 1 : 0;
#pragma unroll
        for (int e = 0; e < NE; e++) if (e != i0 && l[e] > l[i1]) i1 = e;

        float m  = l[i0];
        float e1 = expf(l[i1] - m);
        float s  = 1.0f + e1;
        float g0 = 1.0f / s;
        float g1 = e1 / s;

        int p0 = atomicAdd(&g_count[i0], 1);
        g_tok[i0 * T_TOK + p0]  = t;
        g_gate[i0 * T_TOK + p0] = g0;
        int p1 = atomicAdd(&g_count[i1], 1);
        g_tok[i1 * T_TOK + p1]  = t;
        g_gate[i1 * T_TOK + p1] = g1;
    }
}

// ---------------------------------------------------------------------------
// Prefix offsets over 8 experts
// ---------------------------------------------------------------------------
__global__ void prefix_kernel() {
    if (threadIdx.x == 0) {
        int s = 0;
#pragma unroll
        for (int e = 0; e < NE; e++) { g_off[e] = s; s += g_count[e]; }
    }
}

// ---------------------------------------------------------------------------
// cp.async helpers (16B, zero-fill when pred==false)
// ---------------------------------------------------------------------------
__device__ __forceinline__ void cp16(uint32_t dst_smem, const void* src, bool pred) {
    int sz = pred ? 16 : 0;
    asm volatile("cp.async.cg.shared.global [%0], [%1], 16, %2;\n"
                 :: "r"(dst_smem), "l"(src), "r"(sz));
}
__device__ __forceinline__ void cp_commit() {
    asm volatile("cp.async.commit_group;\n" ::: "memory");
}
__device__ __forceinline__ void cp_wait0() {
    asm volatile("cp.async.wait_group 0;\n" ::: "memory");
}

// ---------------------------------------------------------------------------
// Grouped GEMM, tf32 WMMA.
// Block tile 128x128, BK=16, 4 warps (2x2), warp tile 64x64 (4x4 frags).
// cp.async double-buffered mainloop, 1 syncthreads per k-tile.
// MODE 0: H[row] = gelu(x[tok] @ w1[e] + b1[e])       (N=DFF, K=DM)
// MODE 1: out[tok] += gate * (H[row] @ w2[e] + b2[e])  (N=DM,  K=DFF)
// ---------------------------------------------------------------------------
#define A_LD   24           // 16 cols padded to 24 floats
#define B_LD   136          // 128 cols padded to 136 floats
#define A_SZ   (128 * A_LD) // 3072 floats
#define B_SZ   (16 * B_LD)  // 2176 floats
#define BUF_SZ (A_SZ + B_SZ)// 5248 floats
#define EP_LD  36

template <int MODE>
__global__ void __launch_bounds__(128, 2)
moe_gemm(const float* __restrict__ x,
         const float* __restrict__ W,
         const float* __restrict__ bias,
         float* __restrict__ out) {
    constexpr int N  = (MODE == 0) ? DFF : DM;
    constexpr int KD = (MODE == 0) ? DM  : DFF;
    constexpr int NT = KD / 16;

    const int e   = blockIdx.z;
    const int cnt = g_count[e];
    const int rowBase = blockIdx.y * 128;
    if (rowBase >= cnt) return;
    const int colBase = blockIdx.x * 128;
    const int off = g_off[e];

    __shared__ float sm[2 * BUF_SZ];   // 41KB; epilogue staging overlays this

    const int tid  = threadIdx.x;
    const int warp = tid >> 5;
    const int lane = tid & 31;
    const int wm = warp >> 1, wn = warp & 1;   // 2x2 warp grid, 64x64 per warp

    const float* Wtile = W + (size_t)e * KD * N + colBase;
    const float* Abase = (MODE == 0) ? x : g_H;

    // ---- per-thread gather pointers (hoisted out of k-loop) ----
    // A tile: 512 float4 tiles -> thread handles f = tid + i*128, i=0..3
    //   row = f>>2 = tid/4 + i*32, col4 = (tid&3)*4
    const float* aSrc[4];
    bool         aOk[4];
#pragma unroll
    for (int i = 0; i < 4; i++) {
        int row = (tid >> 2) + i * 32;
        int gr  = rowBase + row;
        bool ok = (gr < cnt);
        size_t arow;
        if (MODE == 0) {
            int tok = ok ? g_tok[e * T_TOK + gr] : 0;
            arow = (size_t)tok * DM;
        } else {
            arow = (size_t)(off + (ok ? gr : 0)) * DFF;
        }
        aSrc[i] = Abase + arow + (tid & 3) * 4;
        aOk[i]  = ok;
    }
    // B tile: f = tid + i*128 -> k = tid/32 + i*4, col4 = (tid&31)*4
    const float* bSrc[4];
#pragma unroll
    for (int i = 0; i < 4; i++) {
        int k = (tid >> 5) + i * 4;
        bSrc[i] = Wtile + (size_t)k * N + (tid & 31) * 4;
    }
    // smem byte destinations (relative to buffer base)
    uint32_t smBase = (uint32_t)__cvta_generic_to_shared(sm);
    uint32_t aDst[4], bDst[4];
#pragma unroll
    for (int i = 0; i < 4; i++) {
        int row = (tid >> 2) + i * 32;
        aDst[i] = (row * A_LD + (tid & 3) * 4) * 4u;
        int k = (tid >> 5) + i * 4;
        bDst[i] = (A_SZ + k * B_LD + (tid & 31) * 4) * 4u;
    }

    wmma::fragment<wmma::accumulator, 16, 16, 8, float> c[4][4];
#pragma unroll
    for (int i = 0; i < 4; i++)
#pragma unroll
        for (int j = 0; j < 4; j++) wmma::fill_fragment(c[i][j], 0.0f);

    // ---- preload tile 0 ----
    {
        uint32_t bb = smBase;  // buffer 0
#pragma unroll
        for (int i = 0; i < 4; i++) cp16(bb + aDst[i], aSrc[i], aOk[i]);
#pragma unroll
        for (int i = 0; i < 4; i++) cp16(bb + bDst[i], bSrc[i], true);
        cp_commit();
    }
    cp_wait0();
    __syncthreads();

    for (int kt = 0; kt < NT; kt++) {
        int cur = kt & 1;
        // ---- issue loads for next tile into the other buffer ----
        if (kt + 1 < NT) {
            uint32_t bb = smBase + (cur ^ 1) * (BUF_SZ * 4u);
            int kOff = (kt + 1) * 16;
#pragma unroll
            for (int i = 0; i < 4; i++) cp16(bb + aDst[i], aSrc[i] + kOff, aOk[i]);
#pragma unroll
            for (int i = 0; i < 4; i++) cp16(bb + bDst[i], bSrc[i] + (size_t)kOff * N, true);
            cp_commit();
        }

        // ---- compute on current buffer ----
        const float* sA = sm + cur * BUF_SZ;
        const float* sB = sA + A_SZ;
#pragma unroll
        for (int ks = 0; ks < 16; ks += 8) {
            wmma::fragment<wmma::matrix_a, 16, 16, 8, wmma::precision::tf32, wmma::row_major> a[4];
            wmma::fragment<wmma::matrix_b, 16, 16, 8, wmma::precision::tf32, wmma::row_major> b[4];
#pragma unroll
            for (int i = 0; i < 4; i++) {
                wmma::load_matrix_sync(a[i], sA + (wm * 64 + i * 16) * A_LD + ks, A_LD);
#pragma unroll
                for (int t2 = 0; t2 < 4; t2++) a[i].x[t2] = wmma::__float_to_tf32(a[i].x[t2]);
            }
#pragma unroll
            for (int j = 0; j < 4; j++) {
                wmma::load_matrix_sync(b[j], sB + ks * B_LD + wn * 64 + j * 16, B_LD);
#pragma unroll
                for (int t2 = 0; t2 < 4; t2++) b[j].x[t2] = wmma::__float_to_tf32(b[j].x[t2]);
            }
#pragma unroll
            for (int i = 0; i < 4; i++)
#pragma unroll
                for (int j = 0; j < 4; j++)
                    wmma::mma_sync(c[i][j], a[i], b[j], c[i][j]);
        }

        if (kt + 1 < NT) cp_wait0();
        __syncthreads();
    }

    // ---- epilogue: per-warp staging (64x32 chunks, 2 passes), private region ----
    float* stage = sm + warp * (64 * EP_LD);
#pragma unroll
    for (int jp = 0; jp < 2; jp++) {
#pragma unroll
        for (int i = 0; i < 4; i++)
#pragma unroll
            for (int jj = 0; jj < 2; jj++)
                wmma::store_matrix_sync(stage + i * 16 * EP_LD + jj * 16,
                                        c[i][2 * jp + jj], EP_LD, wmma::mem_row_major);
        __syncwarp();

        int gcol = colBase + wn * 64 + jp * 32 + lane;
        float bv = bias[e * N + gcol];
#pragma unroll 4
        for (int r = 0; r < 64; r++) {
            int gr = rowBase + wm * 64 + r;
            if (gr < cnt) {
                float v = stage[r * EP_LD + lane] + bv;
                if (MODE == 0) {
                    float g = 0.5f * v * (1.0f + erff(v * 0.70710678118654752f));
                    g_H[(size_t)(off + gr) * DFF + gcol] = g;
                } else {
                    int   tok  = g_tok[e * T_TOK + gr];
                    float gate = g_gate[e * T_TOK + gr];
                    atomicAdd(out + (size_t)tok * DM + gcol, gate * v);
                }
            }
        }
        __syncwarp();
    }
}

// ---------------------------------------------------------------------------
extern "C" void kernel_launch(void* const* d_in, const int* in_sizes, int n_in,
                              void* d_out, int out_size) {
    const float* x  = (const float*)d_in[0];
    const float* rw = (const float*)d_in[1];
    const float* rb = (const float*)d_in[2];
    const float* w1 = (const float*)d_in[3];
    const float* b1 = (const float*)d_in[4];
    const float* w2 = (const float*)d_in[5];
    const float* b2 = (const float*)d_in[6];
    float* out = (float*)d_out;

    init_kernel<<<1024, 256>>>(out, out_size);
    router_kernel<<<512, 256>>>(x, rw, rb);
    prefix_kernel<<<1, 32>>>();
    moe_gemm<0><<<dim3(DFF / 128, T_TOK / 128, NE), 128>>>(x, w1, b1, nullptr);
    moe_gemm<1><<<dim3(DM  / 128, T_TOK / 128, NE), 128>>>(nullptr, w2, b2, out);
}

// round 3
// speedup vs baseline: 4.8296x; 3.1889x over previous
#include <cuda_runtime.h>
#include <cuda_fp16.h>
#include <mma.h>
#include <math.h>
#include <stdint.h>

using namespace nvcuda;

#define T_TOK 4096
#define DM    1024
#define DFF   4096
#define NE    8

// Scratch (static device memory — allowed; no runtime allocation)
__device__ int    g_count[NE];
__device__ int    g_off[NE];
__device__ int    g_tok[NE * T_TOK];
__device__ float  g_gate[NE * T_TOK];
__device__ __half g_xh[(size_t)T_TOK * DM];          //   8 MB
__device__ __half g_w1h[(size_t)NE * DM * DFF];      //  67 MB
__device__ __half g_w2h[(size_t)NE * DFF * DM];      //  67 MB
__device__ __half g_Hh[(size_t)2 * T_TOK * DFF];     //  67 MB

// ---------------------------------------------------------------------------
// Init: zero output accumulator and per-expert counters
// ---------------------------------------------------------------------------
__global__ void init_kernel(float* __restrict__ out, int out_size) {
    int i = blockIdx.x * blockDim.x + threadIdx.x;
    int stride = gridDim.x * blockDim.x;
    for (int j = i; j < out_size; j += stride) out[j] = 0.0f;
    if (blockIdx.x == 0 && threadIdx.x < NE) g_count[threadIdx.x] = 0;
}

// ---------------------------------------------------------------------------
// fp32 -> fp16 conversion (vectorized, grid-stride)
// ---------------------------------------------------------------------------
__global__ void f2h_kernel(const float* __restrict__ src, __half* __restrict__ dst, int n4) {
    int i = blockIdx.x * blockDim.x + threadIdx.x;
    int stride = gridDim.x * blockDim.x;
    for (; i < n4; i += stride) {
        float4 v = ((const float4*)src)[i];
        __half2 h0 = __floats2half2_rn(v.x, v.y);
        __half2 h1 = __floats2half2_rn(v.z, v.w);
        ((__half2*)dst)[2 * i]     = h0;
        ((__half2*)dst)[2 * i + 1] = h1;
    }
}

// ---------------------------------------------------------------------------
// Router: warp per token, fp32 exact logits, top-2 + softmax, append to lists
// ---------------------------------------------------------------------------
__global__ void router_kernel(const float* __restrict__ x,
                              const float* __restrict__ rw,
                              const float* __restrict__ rb) {
    __shared__ float s_rw[DM * NE];  // 32KB
    int tid = threadIdx.x;
    for (int i = tid; i < DM * NE; i += blockDim.x) s_rw[i] = rw[i];
    __syncthreads();

    int warp = tid >> 5, lane = tid & 31;
    int t = blockIdx.x * 8 + warp;     // grid = 512 blocks x 8 warps = 4096
    if (t >= T_TOK) return;

    float acc[NE];
#pragma unroll
    for (int e = 0; e < NE; e++) acc[e] = 0.0f;

    const float* xr = x + (size_t)t * DM;
    for (int d = lane; d < DM; d += 32) {
        float xv = xr[d];
#pragma unroll
        for (int e = 0; e < NE; e++) acc[e] += xv * s_rw[d * NE + e];
    }
#pragma unroll
    for (int e = 0; e < NE; e++) {
#pragma unroll
        for (int o = 16; o > 0; o >>= 1)
            acc[e] += __shfl_xor_sync(0xffffffff, acc[e], o);
    }

    if (lane == 0) {
        float l[NE];
#pragma unroll
        for (int e = 0; e < NE; e++) l[e] = acc[e] + rb[e];
        int i0 = 0;
#pragma unroll
        for (int e = 1; e < NE; e++) if (l[e] > l[i0]) i0 = e;
        int i1 = (i0 == 0) ? 1 : 0;
#pragma unroll
        for (int e = 0; e < NE; e++) if (e != i0 && l[e] > l[i1]) i1 = e;

        float m  = l[i0];
        float e1 = expf(l[i1] - m);
        float s  = 1.0f + e1;
        float g0 = 1.0f / s;
        float g1 = e1 / s;

        int p0 = atomicAdd(&g_count[i0], 1);
        g_tok[i0 * T_TOK + p0]  = t;
        g_gate[i0 * T_TOK + p0] = g0;
        int p1 = atomicAdd(&g_count[i1], 1);
        g_tok[i1 * T_TOK + p1]  = t;
        g_gate[i1 * T_TOK + p1] = g1;
    }
}

// ---------------------------------------------------------------------------
// Prefix offsets over 8 experts
// ---------------------------------------------------------------------------
__global__ void prefix_kernel() {
    if (threadIdx.x == 0) {
        int s = 0;
#pragma unroll
        for (int e = 0; e < NE; e++) { g_off[e] = s; s += g_count[e]; }
    }
}

// ---------------------------------------------------------------------------
// cp.async helpers (16B, zero-fill when pred==false)
// ---------------------------------------------------------------------------
__device__ __forceinline__ void cp16(uint32_t dst_smem, const void* src, bool pred) {
    int sz = pred ? 16 : 0;
    asm volatile("cp.async.cg.shared.global [%0], [%1], 16, %2;\n"
                 :: "r"(dst_smem), "l"(src), "r"(sz));
}
__device__ __forceinline__ void cp_commit() {
    asm volatile("cp.async.commit_group;\n" ::: "memory");
}
__device__ __forceinline__ void cp_wait0() {
    asm volatile("cp.async.wait_group 0;\n" ::: "memory");
}

// ---------------------------------------------------------------------------
// Grouped GEMM, fp16 WMMA (m16n16k16), fp32 accumulate.
// Block tile 128x128, BK=32, 8 warps (2x4), warp tile 64x32 (4x2 frags).
// cp.async double-buffered mainloop, 1 syncthreads per k-tile.
// MODE 0: H[row] = gelu(xh[tok] @ w1h[e] + b1[e])       (N=DFF, K=DM)
// MODE 1: out[tok] += gate * (Hh[row] @ w2h[e] + b2[e])  (N=DM,  K=DFF)
// ---------------------------------------------------------------------------
#define A_LD   40            // 32 halves padded to 40 (80B rows: conflict-free LDSM)
#define B_LD   136           // 128 halves padded to 136 (272B rows)
#define A_SZ   (128 * A_LD)  // 5120 halves
#define B_SZ   (32 * B_LD)   // 4352 halves
#define BUF_SZ (A_SZ + B_SZ) // 9472 halves = 18944 B
#define EP_LD  40            // epilogue stage: 16 x 40 fp32 per warp

template <int MODE>
__global__ void __launch_bounds__(256, 2)
moe_gemm(const __half* __restrict__ Wh,
         const float* __restrict__ bias,
         float* __restrict__ out) {
    constexpr int N  = (MODE == 0) ? DFF : DM;
    constexpr int KD = (MODE == 0) ? DM  : DFF;
    constexpr int NT = KD / 32;

    const int e   = blockIdx.z;
    const int cnt = g_count[e];
    const int rowBase = blockIdx.y * 128;
    if (rowBase >= cnt) return;
    const int colBase = blockIdx.x * 128;
    const int off = g_off[e];

    __shared__ __align__(16) __half sm[2 * BUF_SZ];   // 37.9 KB; epilogue overlays

    const int tid  = threadIdx.x;
    const int warp = tid >> 5;
    const int lane = tid & 31;
    const int wm = warp >> 2, wn = warp & 3;   // 2x4 warp grid, 64x32 per warp

    const __half* Wtile = Wh + (size_t)e * KD * N + colBase;
    const __half* Abase = (MODE == 0) ? g_xh : g_Hh;

    // ---- per-thread gather pointers (hoisted out of k-loop) ----
    // A tile: 512 x 16B chunks. f = tid + i*256 -> row = f>>2, col8 = (f&3)*8
    const __half* aSrc[2];
    bool          aOk[2];
#pragma unroll
    for (int i = 0; i < 2; i++) {
        int row = (tid >> 2) + i * 64;
        int gr  = rowBase + row;
        bool ok = (gr < cnt);
        size_t arow;
        if (MODE == 0) {
            int tok = ok ? g_tok[e * T_TOK + gr] : 0;
            arow = (size_t)tok * DM;
        } else {
            arow = (size_t)(off + (ok ? gr : 0)) * DFF;
        }
        aSrc[i] = Abase + arow + (tid & 3) * 8;
        aOk[i]  = ok;
    }
    // B tile: 512 x 16B chunks. f = tid + i*256 -> k = f>>4, col8 = (f&15)*8
    const __half* bSrc[2];
#pragma unroll
    for (int i = 0; i < 2; i++) {
        int k = (tid >> 4) + i * 16;
        bSrc[i] = Wtile + (size_t)k * N + (tid & 15) * 8;
    }
    uint32_t smBase = (uint32_t)__cvta_generic_to_shared(sm);
    uint32_t aDst[2], bDst[2];
#pragma unroll
    for (int i = 0; i < 2; i++) {
        int row = (tid >> 2) + i * 64;
        aDst[i] = (row * A_LD + (tid & 3) * 8) * 2u;
        int k = (tid >> 4) + i * 16;
        bDst[i] = (A_SZ + k * B_LD + (tid & 15) * 8) * 2u;
    }

    wmma::fragment<wmma::accumulator, 16, 16, 16, float> c[4][2];
#pragma unroll
    for (int i = 0; i < 4; i++)
#pragma unroll
        for (int j = 0; j < 2; j++) wmma::fill_fragment(c[i][j], 0.0f);

    // ---- preload tile 0 ----
    {
        uint32_t bb = smBase;
#pragma unroll
        for (int i = 0; i < 2; i++) cp16(bb + aDst[i], aSrc[i], aOk[i]);
#pragma unroll
        for (int i = 0; i < 2; i++) cp16(bb + bDst[i], bSrc[i], true);
        cp_commit();
    }
    cp_wait0();
    __syncthreads();

    for (int kt = 0; kt < NT; kt++) {
        int cur = kt & 1;
        // ---- issue loads for next tile into the other buffer ----
        if (kt + 1 < NT) {
            uint32_t bb = smBase + (cur ^ 1) * (BUF_SZ * 2u);
            int kOff = (kt + 1) * 32;
#pragma unroll
            for (int i = 0; i < 2; i++) cp16(bb + aDst[i], aSrc[i] + kOff, aOk[i]);
#pragma unroll
            for (int i = 0; i < 2; i++) cp16(bb + bDst[i], bSrc[i] + (size_t)kOff * N, true);
            cp_commit();
        }

        // ---- compute on current buffer ----
        const __half* sA = sm + cur * BUF_SZ;
        const __half* sB = sA + A_SZ;
#pragma unroll
        for (int ks = 0; ks < 32; ks += 16) {
            wmma::fragment<wmma::matrix_a, 16, 16, 16, __half, wmma::row_major> a[4];
            wmma::fragment<wmma::matrix_b, 16, 16, 16, __half, wmma::row_major> b[2];
#pragma unroll
            for (int i = 0; i < 4; i++)
                wmma::load_matrix_sync(a[i], sA + (wm * 64 + i * 16) * A_LD + ks, A_LD);
#pragma unroll
            for (int j = 0; j < 2; j++)
                wmma::load_matrix_sync(b[j], sB + ks * B_LD + wn * 32 + j * 16, B_LD);
#pragma unroll
            for (int i = 0; i < 4; i++)
#pragma unroll
                for (int j = 0; j < 2; j++)
                    wmma::mma_sync(c[i][j], a[i], b[j], c[i][j]);
        }

        if (kt + 1 < NT) cp_wait0();
        __syncthreads();
    }

    // ---- epilogue: per-warp 16x32 staging (fp32), 4 passes over m-frags ----
    float* stage = (float*)sm + warp * (16 * EP_LD);
    int gcol = colBase + wn * 32 + lane;
    float bv = bias[e * N + gcol];

#pragma unroll
    for (int i = 0; i < 4; i++) {
#pragma unroll
        for (int j = 0; j < 2; j++)
            wmma::store_matrix_sync(stage + j * 16, c[i][j], EP_LD, wmma::mem_row_major);
        __syncwarp();
#pragma unroll
        for (int r = 0; r < 16; r++) {
            int gr = rowBase + wm * 64 + i * 16 + r;
            if (gr < cnt) {
                float v = stage[r * EP_LD + lane] + bv;
                if (MODE == 0) {
                    float g = 0.5f * v * (1.0f + erff(v * 0.70710678118654752f));
                    g_Hh[(size_t)(off + gr) * DFF + gcol] = __float2half_rn(g);
                } else {
                    int   tok  = g_tok[e * T_TOK + gr];
                    float gate = g_gate[e * T_TOK + gr];
                    atomicAdd(out + (size_t)tok * DM + gcol, gate * v);
                }
            }
        }
        __syncwarp();
    }
}

// ---------------------------------------------------------------------------
extern "C" void kernel_launch(void* const* d_in, const int* in_sizes, int n_in,
                              void* d_out, int out_size) {
    const float* x  = (const float*)d_in[0];
    const float* rw = (const float*)d_in[1];
    const float* rb = (const float*)d_in[2];
    const float* w1 = (const float*)d_in[3];
    const float* b1 = (const float*)d_in[4];
    const float* w2 = (const float*)d_in[5];
    const float* b2 = (const float*)d_in[6];
    float* out = (float*)d_out;

    __half* xh;  cudaGetSymbolAddress((void**)&xh,  g_xh);
    __half* w1h; cudaGetSymbolAddress((void**)&w1h, g_w1h);
    __half* w2h; cudaGetSymbolAddress((void**)&w2h, g_w2h);

    init_kernel<<<1024, 256>>>(out, out_size);
    f2h_kernel<<<2048, 256>>>(x,  xh,  T_TOK * DM / 4);
    f2h_kernel<<<2048, 256>>>(w1, w1h, NE * DM * DFF / 4);
    f2h_kernel<<<2048, 256>>>(w2, w2h, NE * DFF * DM / 4);
    router_kernel<<<512, 256>>>(x, rw, rb);
    prefix_kernel<<<1, 32>>>();
    moe_gemm<0><<<dim3(DFF / 128, T_TOK / 128, NE), 256>>>(w1h, b1, nullptr);
    moe_gemm<1><<<dim3(DM  / 128, T_TOK / 128, NE), 256>>>(w2h, b2, out);
}

// round 6
// speedup vs baseline: 5.0159x; 1.0386x over previous
#include <cuda_runtime.h>
#include <cuda_fp16.h>
#include <mma.h>
#include <math.h>
#include <stdint.h>

using namespace nvcuda;

#define T_TOK 4096
#define DM    1024
#define DFF   4096
#define NE    8

// Scratch (static device memory — allowed; no runtime allocation)
__device__ int    g_count[NE];
__device__ int    g_off[NE];
__device__ int    g_tok[NE * T_TOK];
__device__ float  g_gate[NE * T_TOK];
__device__ __half g_xh[(size_t)T_TOK * DM];          //   8 MB
__device__ __half g_w1h[(size_t)NE * DM * DFF];      //  67 MB  [E][K][N]
__device__ __half g_w2h[(size_t)NE * DFF * DM];      //  67 MB  [E][K][N]
__device__ __half g_Hh[(size_t)2 * T_TOK * DFF];     //  67 MB

__device__ __forceinline__ uint32_t h2_bits(__half2 h) {
    union { __half2 h; uint32_t u; } cvt;
    cvt.h = h;
    return cvt.u;
}

// ---------------------------------------------------------------------------
__global__ void init_kernel(float* __restrict__ out, int out_size) {
    int i = blockIdx.x * blockDim.x + threadIdx.x;
    int stride = gridDim.x * blockDim.x;
    for (int j = i; j < out_size; j += stride) out[j] = 0.0f;
    if (blockIdx.x == 0 && threadIdx.x < NE) g_count[threadIdx.x] = 0;
}

// fp32 -> fp16, 32B loads / 16B stores per iter
__global__ void f2h_kernel(const float* __restrict__ src, __half* __restrict__ dst, int n8) {
    int i = blockIdx.x * blockDim.x + threadIdx.x;
    int stride = gridDim.x * blockDim.x;
    for (; i < n8; i += stride) {
        float4 v0 = ((const float4*)src)[2 * i];
        float4 v1 = ((const float4*)src)[2 * i + 1];
        uint4 o;
        o.x = h2_bits(__floats2half2_rn(v0.x, v0.y));
        o.y = h2_bits(__floats2half2_rn(v0.z, v0.w));
        o.z = h2_bits(__floats2half2_rn(v1.x, v1.y));
        o.w = h2_bits(__floats2half2_rn(v1.z, v1.w));
        ((uint4*)dst)[i] = o;
    }
}

// ---------------------------------------------------------------------------
// Router: warp per token, fp32 exact logits, top-2 + softmax, append to lists
// ---------------------------------------------------------------------------
__global__ void router_kernel(const float* __restrict__ x,
                              const float* __restrict__ rw,
                              const float* __restrict__ rb) {
    __shared__ float s_rw[DM * NE];
    int tid = threadIdx.x;
    for (int i = tid; i < DM * NE; i += blockDim.x) s_rw[i] = rw[i];
    __syncthreads();

    int warp = tid >> 5, lane = tid & 31;
    int t = blockIdx.x * 8 + warp;
    if (t >= T_TOK) return;

    float acc[NE];
#pragma unroll
    for (int e = 0; e < NE; e++) acc[e] = 0.0f;
    const float* xr = x + (size_t)t * DM;
    for (int d = lane; d < DM; d += 32) {
        float xv = xr[d];
#pragma unroll
        for (int e = 0; e < NE; e++) acc[e] += xv * s_rw[d * NE + e];
    }
#pragma unroll
    for (int e = 0; e < NE; e++) {
#pragma unroll
        for (int o = 16; o > 0; o >>= 1) acc[e] += __shfl_xor_sync(0xffffffff, acc[e], o);
    }
    if (lane == 0) {
        float l[NE];
#pragma unroll
        for (int e = 0; e < NE; e++) l[e] = acc[e] + rb[e];
        int i0 = 0;
#pragma unroll
        for (int e = 1; e < NE; e++) if (l[e] > l[i0]) i0 = e;
        int i1 = (i0 == 0) ? 1 : 0;
#pragma unroll
        for (int e = 0; e < NE; e++) if (e != i0 && l[e] > l[i1]) i1 = e;
        float m = l[i0], e1 = expf(l[i1] - m), s = 1.0f + e1;
        int p0 = atomicAdd(&g_count[i0], 1);
        g_tok[i0 * T_TOK + p0] = t;  g_gate[i0 * T_TOK + p0] = 1.0f / s;
        int p1 = atomicAdd(&g_count[i1], 1);
        g_tok[i1 * T_TOK + p1] = t;  g_gate[i1 * T_TOK + p1] = e1 / s;
    }
}

__global__ void prefix_kernel() {
    if (threadIdx.x == 0) {
        int s = 0;
#pragma unroll
        for (int e = 0; e < NE; e++) { g_off[e] = s; s += g_count[e]; }
    }
}

// ---------------------------------------------------------------------------
// cp.async helpers (16B, zero-fill when pred==false)
// ---------------------------------------------------------------------------
__device__ __forceinline__ void cp16(uint32_t dst_smem, const void* src, bool pred) {
    int sz = pred ? 16 : 0;
    asm volatile("cp.async.cg.shared.global [%0], [%1], 16, %2;\n"
                 :: "r"(dst_smem), "l"(src), "r"(sz));
}
__device__ __forceinline__ void cp_commit() {
    asm volatile("cp.async.commit_group;\n" ::: "memory");
}
__device__ __forceinline__ void cp_wait1() {
    asm volatile("cp.async.wait_group 1;\n" ::: "memory");
}
__device__ __forceinline__ void cp_wait0() {
    asm volatile("cp.async.wait_group 0;\n" ::: "memory");
}

// ---------------------------------------------------------------------------
// Grouped GEMM, fp16 WMMA (m16n16k16), fp32 accumulate.
// Block tile 128x128, BK=32, 8 warps (2x4), warp tile 64x32 (4x2 frags).
// 3-stage cp.async pipeline, issue-before-compute, 1 syncthreads / k-tile.
// MODE 0: H[row] = gelu(xh[tok] @ w1h[e] + b1[e])       (N=DFF, K=DM)
// MODE 1: out[tok] += gate * (Hh[row] @ w2h[e] + b2[e])  (N=DM,  K=DFF) split-K
// ---------------------------------------------------------------------------
#define A_LD   40            // 32 halves padded to 40 (conflict-free LDSM)
#define B_LD   136           // 128 halves padded to 136
#define A_SZ   (128 * A_LD)  // 5120 halves
#define B_SZ   (32 * B_LD)   // 4352 halves
#define BUF_SZ (A_SZ + B_SZ) // 9472 halves = 18944 B
#define NSTAGE 3
#define GEMM_SMEM (NSTAGE * BUF_SZ * 2)   // 56832 B
#define EP_LD  40

template <int MODE, int SPLITS>
__global__ void __launch_bounds__(256, 2)
moe_gemm(const __half* __restrict__ Wh,
         const float* __restrict__ bias,
         float* __restrict__ out) {
    constexpr int N   = (MODE == 0) ? DFF : DM;
    constexpr int KDT = (MODE == 0) ? DM  : DFF;
    constexpr int KD  = KDT / SPLITS;
    constexpr int NT  = KD / 32;
    constexpr int CT  = N / 128;

    const int e   = blockIdx.z;
    const int cnt = g_count[e];
    const int rowBase = blockIdx.y * 128;
    if (rowBase >= cnt) return;
    const int split   = blockIdx.x / CT;
    const int colBase = (blockIdx.x % CT) * 128;
    const int kStart  = split * KD;
    const int off = g_off[e];

    extern __shared__ __align__(16) char smraw[];
    __half* sm = (__half*)smraw;

    const int tid  = threadIdx.x;
    const int warp = tid >> 5;
    const int lane = tid & 31;
    const int wm = warp >> 2, wn = warp & 3;

    const __half* Wtile = Wh + (size_t)e * KDT * N + (size_t)kStart * N + colBase;
    const __half* Abase = (MODE == 0) ? g_xh : g_Hh;

    // ---- per-thread gather pointers ----
    const __half* aSrc[2];
    bool          aOk[2];
#pragma unroll
    for (int i = 0; i < 2; i++) {
        int row = (tid >> 2) + i * 64;
        int gr  = rowBase + row;
        bool ok = (gr < cnt);
        size_t arow;
        if (MODE == 0) arow = (size_t)(ok ? g_tok[e * T_TOK + gr] : 0) * DM;
        else           arow = (size_t)(off + (ok ? gr : 0)) * DFF;
        aSrc[i] = Abase + arow + kStart + (tid & 3) * 8;
        aOk[i]  = ok;
    }
    const __half* bSrc[2];
#pragma unroll
    for (int i = 0; i < 2; i++) {
        int k = (tid >> 4) + i * 16;
        bSrc[i] = Wtile + (size_t)k * N + (tid & 15) * 8;
    }
    uint32_t smBase = (uint32_t)__cvta_generic_to_shared(sm);
    uint32_t aDst[2], bDst[2];
#pragma unroll
    for (int i = 0; i < 2; i++) {
        int row = (tid >> 2) + i * 64;
        aDst[i] = (row * A_LD + (tid & 3) * 8) * 2u;
        int k = (tid >> 4) + i * 16;
        bDst[i] = (A_SZ + k * B_LD + (tid & 15) * 8) * 2u;
    }

    auto load_stage = [&](int buf, int kt) {
        uint32_t bb = smBase + buf * (BUF_SZ * 2u);
        int kOff = kt * 32;
#pragma unroll
        for (int i = 0; i < 2; i++) cp16(bb + aDst[i], aSrc[i] + kOff, aOk[i]);
#pragma unroll
        for (int i = 0; i < 2; i++) cp16(bb + bDst[i], bSrc[i] + (size_t)kOff * N, true);
        cp_commit();
    };

    wmma::fragment<wmma::accumulator, 16, 16, 16, float> c[4][2];
#pragma unroll
    for (int i = 0; i < 4; i++)
#pragma unroll
        for (int j = 0; j < 2; j++) wmma::fill_fragment(c[i][j], 0.0f);

    // ---- prologue: stages 0 and 1 in flight ----
    load_stage(0, 0);
    load_stage(1, 1);

#pragma unroll 1
    for (int s = 0; s < NT; s++) {
        if (s + 1 < NT) cp_wait1(); else cp_wait0();   // stage s resident
        __syncthreads();                                // also protects buf (s+2)%3 reuse
        if (s + 2 < NT) load_stage((s + 2) % NSTAGE, s + 2);

        const __half* sA = sm + (s % NSTAGE) * BUF_SZ;
        const __half* sB = sA + A_SZ;
#pragma unroll
        for (int ks = 0; ks < 32; ks += 16) {
            wmma::fragment<wmma::matrix_a, 16, 16, 16, __half, wmma::row_major> a[4];
            wmma::fragment<wmma::matrix_b, 16, 16, 16, __half, wmma::row_major> b[2];
#pragma unroll
            for (int i = 0; i < 4; i++)
                wmma::load_matrix_sync(a[i], sA + (wm * 64 + i * 16) * A_LD + ks, A_LD);
#pragma unroll
            for (int j = 0; j < 2; j++)
                wmma::load_matrix_sync(b[j], sB + ks * B_LD + wn * 32 + j * 16, B_LD);
#pragma unroll
            for (int i = 0; i < 4; i++)
#pragma unroll
                for (int j = 0; j < 2; j++)
                    wmma::mma_sync(c[i][j], a[i], b[j], c[i][j]);
        }
    }
    __syncthreads();   // all warps done reading buffers before epilogue staging

    // ---- epilogue: per-warp 16x32 staging (fp32), 4 passes over m-frags ----
    float* stage = (float*)sm + warp * (16 * EP_LD);
    int gcol = colBase + wn * 32 + lane;
    float bv = bias[e * N + gcol];
    if (MODE == 1 && split != 0) bv = 0.0f;     // bias added once (split 0)

#pragma unroll
    for (int i = 0; i < 4; i++) {
#pragma unroll
        for (int j = 0; j < 2; j++)
            wmma::store_matrix_sync(stage + j * 16, c[i][j], EP_LD, wmma::mem_row_major);
        __syncwarp();
#pragma unroll
        for (int r = 0; r < 16; r++) {
            int gr = rowBase + wm * 64 + i * 16 + r;
            if (gr < cnt) {
                float v = stage[r * EP_LD + lane] + bv;
                if (MODE == 0) {
                    float g = 0.5f * v * (1.0f + erff(v * 0.70710678118654752f));
                    g_Hh[(size_t)(off + gr) * DFF + gcol] = __float2half_rn(g);
                } else {
                    int   tok  = g_tok[e * T_TOK + gr];
                    float gate = g_gate[e * T_TOK + gr];
                    atomicAdd(out + (size_t)tok * DM + gcol, gate * v);
                }
            }
        }
        __syncwarp();
    }
}

// ---------------------------------------------------------------------------
extern "C" void kernel_launch(void* const* d_in, const int* in_sizes, int n_in,
                              void* d_out, int out_size) {
    const float* x  = (const float*)d_in[0];
    const float* rw = (const float*)d_in[1];
    const float* rb = (const float*)d_in[2];
    const float* w1 = (const float*)d_in[3];
    const float* b1 = (const float*)d_in[4];
    const float* w2 = (const float*)d_in[5];
    const float* b2 = (const float*)d_in[6];
    float* out = (float*)d_out;

    __half *xh, *w1h, *w2h;
    cudaGetSymbolAddress((void**)&xh,  g_xh);
    cudaGetSymbolAddress((void**)&w1h, g_w1h);
    cudaGetSymbolAddress((void**)&w2h, g_w2h);

    cudaFuncSetAttribute(moe_gemm<0, 1>, cudaFuncAttributeMaxDynamicSharedMemorySize, GEMM_SMEM);
    cudaFuncSetAttribute(moe_gemm<1, 2>, cudaFuncAttributeMaxDynamicSharedMemorySize, GEMM_SMEM);

    init_kernel<<<1024, 256>>>(out, out_size);
    f2h_kernel<<<512, 256>>>(x,  xh,  T_TOK * DM / 8);
    f2h_kernel<<<2048, 256>>>(w1, w1h, NE * DM * DFF / 8);
    f2h_kernel<<<2048, 256>>>(w2, w2h, NE * DFF * DM / 8);
    router_kernel<<<512, 256>>>(x, rw, rb);
    prefix_kernel<<<1, 32>>>();
    moe_gemm<0, 1><<<dim3(DFF / 128,     T_TOK / 128, NE), 256, GEMM_SMEM>>>(w1h, b1, nullptr);
    moe_gemm<1, 2><<<dim3(2 * (DM / 128), T_TOK / 128, NE), 256, GEMM_SMEM>>>(w2h, b2, out);
}

// round 7
// speedup vs baseline: 5.0193x; 1.0007x over previous
#include <cuda_runtime.h>
#include <cuda_fp16.h>
#include <mma.h>
#include <math.h>
#include <stdint.h>

using namespace nvcuda;

#define T_TOK 4096
#define DM    1024
#define DFF   4096
#define NE    8
#define MAXTILE 80

// Scratch (static device memory — allowed; no runtime allocation)
__device__ int    g_count[NE];
__device__ int    g_off[NE];
__device__ int    g_ntiles;
__device__ int    g_tile_e[MAXTILE];
__device__ int    g_tile_rb[MAXTILE];
__device__ int    g_tok[NE * T_TOK];
__device__ int    g_te0[T_TOK], g_te1[T_TOK];
__device__ int    g_tp0[T_TOK], g_tp1[T_TOK];
__device__ float  g_tg0[T_TOK], g_tg1[T_TOK];
__device__ __half g_xh[(size_t)T_TOK * DM];          //   8 MB
__device__ __half g_w1h[(size_t)NE * DM * DFF];      //  67 MB  [E][K][N]
__device__ __half g_w2h[(size_t)NE * DFF * DM];      //  67 MB  [E][K][N]
__device__ __half g_Hh[(size_t)2 * T_TOK * DFF];     //  67 MB
__device__ float  g_y[(size_t)2 * T_TOK * DM];       //  33.5 MB

__device__ __forceinline__ uint32_t h2_bits(__half2 h) {
    union { __half2 h; uint32_t u; } cvt;
    cvt.h = h;
    return cvt.u;
}

// ---------------------------------------------------------------------------
__global__ void init_kernel() {
    if (threadIdx.x < NE) g_count[threadIdx.x] = 0;
}

// fp32 -> fp16, 32B loads / 16B stores per iter
__global__ void f2h_kernel(const float* __restrict__ src, __half* __restrict__ dst, int n8) {
    int i = blockIdx.x * blockDim.x + threadIdx.x;
    int stride = gridDim.x * blockDim.x;
    for (; i < n8; i += stride) {
        float4 v0 = ((const float4*)src)[2 * i];
        float4 v1 = ((const float4*)src)[2 * i + 1];
        uint4 o;
        o.x = h2_bits(__floats2half2_rn(v0.x, v0.y));
        o.y = h2_bits(__floats2half2_rn(v0.z, v0.w));
        o.z = h2_bits(__floats2half2_rn(v1.x, v1.y));
        o.w = h2_bits(__floats2half2_rn(v1.z, v1.w));
        ((uint4*)dst)[i] = o;
    }
}

// ---------------------------------------------------------------------------
// Router: warp per token, fp32 exact logits, top-2 + softmax.
// Appends to per-expert row lists AND records per-token (e, pos, gate) pairs.
// ---------------------------------------------------------------------------
__global__ void router_kernel(const float* __restrict__ x,
                              const float* __restrict__ rw,
                              const float* __restrict__ rb) {
    __shared__ float s_rw[DM * NE];
    int tid = threadIdx.x;
    for (int i = tid; i < DM * NE; i += blockDim.x) s_rw[i] = rw[i];
    __syncthreads();

    int warp = tid >> 5, lane = tid & 31;
    int t = blockIdx.x * 8 + warp;
    if (t >= T_TOK) return;

    float acc[NE];
#pragma unroll
    for (int e = 0; e < NE; e++) acc[e] = 0.0f;
    const float* xr = x + (size_t)t * DM;
    for (int d = lane; d < DM; d += 32) {
        float xv = xr[d];
#pragma unroll
        for (int e = 0; e < NE; e++) acc[e] += xv * s_rw[d * NE + e];
    }
#pragma unroll
    for (int e = 0; e < NE; e++) {
#pragma unroll
        for (int o = 16; o > 0; o >>= 1) acc[e] += __shfl_xor_sync(0xffffffff, acc[e], o);
    }
    if (lane == 0) {
        float l[NE];
#pragma unroll
        for (int e = 0; e < NE; e++) l[e] = acc[e] + rb[e];
        int i0 = 0;
#pragma unroll
        for (int e = 1; e < NE; e++) if (l[e] > l[i0]) i0 = e;
        int i1 = (i0 == 0) ? 1 : 0;
#pragma unroll
        for (int e = 0; e < NE; e++) if (e != i0 && l[e] > l[i1]) i1 = e;
        float m = l[i0], e1 = expf(l[i1] - m), s = 1.0f + e1;

        int p0 = atomicAdd(&g_count[i0], 1);
        g_tok[i0 * T_TOK + p0] = t;
        int p1 = atomicAdd(&g_count[i1], 1);
        g_tok[i1 * T_TOK + p1] = t;

        g_te0[t] = i0; g_tp0[t] = p0; g_tg0[t] = 1.0f / s;
        g_te1[t] = i1; g_tp1[t] = p1; g_tg1[t] = e1 / s;
    }
}

// Prefix offsets + flat tile table (only real 128-row tiles)
__global__ void prefix_kernel() {
    if (threadIdx.x == 0) {
        int s = 0, nt = 0;
#pragma unroll
        for (int e = 0; e < NE; e++) {
            g_off[e] = s;
            int c = g_count[e];
            for (int rb = 0; rb < c; rb += 128) {
                g_tile_e[nt]  = e;
                g_tile_rb[nt] = rb;
                nt++;
            }
            s += c;
        }
        g_ntiles = nt;
    }
}

// ---------------------------------------------------------------------------
// cp.async helpers (16B, zero-fill when pred==false)
// ---------------------------------------------------------------------------
__device__ __forceinline__ void cp16(uint32_t dst_smem, const void* src, bool pred) {
    int sz = pred ? 16 : 0;
    asm volatile("cp.async.cg.shared.global [%0], [%1], 16, %2;\n"
                 :: "r"(dst_smem), "l"(src), "r"(sz));
}
__device__ __forceinline__ void cp_commit() {
    asm volatile("cp.async.commit_group;\n" ::: "memory");
}
__device__ __forceinline__ void cp_wait1() {
    asm volatile("cp.async.wait_group 1;\n" ::: "memory");
}
__device__ __forceinline__ void cp_wait0() {
    asm volatile("cp.async.wait_group 0;\n" ::: "memory");
}

// ---------------------------------------------------------------------------
// Grouped GEMM, fp16 WMMA (m16n16k16), fp32 accumulate.
// Block tile 128x128, BK=32, 8 warps (2x4), warp tile 64x32 (4x2 frags).
// 3-stage cp.async pipeline; tiles come from the flat (expert,rowBase) table.
// MODE 0: H[row] = gelu(xh[tok] @ w1h[e] + b1[e])   (N=DFF, K=DM)
// MODE 1: y[row]  =       Hh[row] @ w2h[e] + b2[e]  (N=DM,  K=DFF)
// ---------------------------------------------------------------------------
#define A_LD   40
#define B_LD   136
#define A_SZ   (128 * A_LD)
#define B_SZ   (32 * B_LD)
#define BUF_SZ (A_SZ + B_SZ)
#define NSTAGE 3
#define GEMM_SMEM (NSTAGE * BUF_SZ * 2)
#define EP_LD  40

template <int MODE>
__global__ void __launch_bounds__(256, 2)
moe_gemm(const __half* __restrict__ Wh,
         const float* __restrict__ bias) {
    constexpr int N  = (MODE == 0) ? DFF : DM;
    constexpr int KD = (MODE == 0) ? DM  : DFF;
    constexpr int NT = KD / 32;

    const int tileIdx = blockIdx.y;
    if (tileIdx >= g_ntiles) return;
    const int e       = g_tile_e[tileIdx];
    const int rowBase = g_tile_rb[tileIdx];
    const int cnt     = g_count[e];
    const int colBase = blockIdx.x * 128;
    const int off     = g_off[e];

    extern __shared__ __align__(16) char smraw[];
    __half* sm = (__half*)smraw;

    const int tid  = threadIdx.x;
    const int warp = tid >> 5;
    const int lane = tid & 31;
    const int wm = warp >> 2, wn = warp & 3;

    const __half* Wtile = Wh + (size_t)e * KD * N + colBase;
    const __half* Abase = (MODE == 0) ? g_xh : g_Hh;

    // ---- per-thread gather pointers ----
    const __half* aSrc[2];
    bool          aOk[2];
#pragma unroll
    for (int i = 0; i < 2; i++) {
        int row = (tid >> 2) + i * 64;
        int gr  = rowBase + row;
        bool ok = (gr < cnt);
        size_t arow;
        if (MODE == 0) arow = (size_t)(ok ? g_tok[e * T_TOK + gr] : 0) * DM;
        else           arow = (size_t)(off + (ok ? gr : 0)) * DFF;
        aSrc[i] = Abase + arow + (tid & 3) * 8;
        aOk[i]  = ok;
    }
    const __half* bSrc[2];
#pragma unroll
    for (int i = 0; i < 2; i++) {
        int k = (tid >> 4) + i * 16;
        bSrc[i] = Wtile + (size_t)k * N + (tid & 15) * 8;
    }
    uint32_t smBase = (uint32_t)__cvta_generic_to_shared(sm);
    uint32_t aDst[2], bDst[2];
#pragma unroll
    for (int i = 0; i < 2; i++) {
        int row = (tid >> 2) + i * 64;
        aDst[i] = (row * A_LD + (tid & 3) * 8) * 2u;
        int k = (tid >> 4) + i * 16;
        bDst[i] = (A_SZ + k * B_LD + (tid & 15) * 8) * 2u;
    }

    auto load_stage = [&](int buf, int kt) {
        uint32_t bb = smBase + buf * (BUF_SZ * 2u);
        int kOff = kt * 32;
#pragma unroll
        for (int i = 0; i < 2; i++) cp16(bb + aDst[i], aSrc[i] + kOff, aOk[i]);
#pragma unroll
        for (int i = 0; i < 2; i++) cp16(bb + bDst[i], bSrc[i] + (size_t)kOff * N, true);
        cp_commit();
    };

    wmma::fragment<wmma::accumulator, 16, 16, 16, float> c[4][2];
#pragma unroll
    for (int i = 0; i < 4; i++)
#pragma unroll
        for (int j = 0; j < 2; j++) wmma::fill_fragment(c[i][j], 0.0f);

    load_stage(0, 0);
    load_stage(1, 1);

#pragma unroll 1
    for (int s = 0; s < NT; s++) {
        if (s + 1 < NT) cp_wait1(); else cp_wait0();
        __syncthreads();
        if (s + 2 < NT) load_stage((s + 2) % NSTAGE, s + 2);

        const __half* sA = sm + (s % NSTAGE) * BUF_SZ;
        const __half* sB = sA + A_SZ;
#pragma unroll
        for (int ks = 0; ks < 32; ks += 16) {
            wmma::fragment<wmma::matrix_a, 16, 16, 16, __half, wmma::row_major> a[4];
            wmma::fragment<wmma::matrix_b, 16, 16, 16, __half, wmma::row_major> b[2];
#pragma unroll
            for (int i = 0; i < 4; i++)
                wmma::load_matrix_sync(a[i], sA + (wm * 64 + i * 16) * A_LD + ks, A_LD);
#pragma unroll
            for (int j = 0; j < 2; j++)
                wmma::load_matrix_sync(b[j], sB + ks * B_LD + wn * 32 + j * 16, B_LD);
#pragma unroll
            for (int i = 0; i < 4; i++)
#pragma unroll
                for (int j = 0; j < 2; j++)
                    wmma::mma_sync(c[i][j], a[i], b[j], c[i][j]);
        }
    }
    __syncthreads();

    // ---- epilogue: per-warp 16x32 staging (fp32), 4 passes over m-frags ----
    float* stage = (float*)sm + warp * (16 * EP_LD);
    int gcol = colBase + wn * 32 + lane;
    float bv = bias[e * N + gcol];

#pragma unroll
    for (int i = 0; i < 4; i++) {
#pragma unroll
        for (int j = 0; j < 2; j++)
            wmma::store_matrix_sync(stage + j * 16, c[i][j], EP_LD, wmma::mem_row_major);
        __syncwarp();
#pragma unroll
        for (int r = 0; r < 16; r++) {
            int gr = rowBase + wm * 64 + i * 16 + r;
            if (gr < cnt) {
                float v = stage[r * EP_LD + lane] + bv;
                if (MODE == 0) {
                    float g = 0.5f * v * (1.0f + erff(v * 0.70710678118654752f));
                    g_Hh[(size_t)(off + gr) * DFF + gcol] = __float2half_rn(g);
                } else {
                    g_y[(size_t)(off + gr) * DM + gcol] = v;
                }
            }
        }
        __syncwarp();
    }
}

// ---------------------------------------------------------------------------
// Mix: out[t] = g0 * y[r0] + g1 * y[r1]   (bias already in y)
// ---------------------------------------------------------------------------
__global__ void mix_kernel(float* __restrict__ out) {
    int idx = blockIdx.x * blockDim.x + threadIdx.x;    // over T_TOK * DM/4
    int t  = idx >> 8;                                  // DM/4 = 256
    int c4 = (idx & 255) * 4;
    float g0 = g_tg0[t], g1 = g_tg1[t];
    size_t r0 = (size_t)(g_off[g_te0[t]] + g_tp0[t]) * DM + c4;
    size_t r1 = (size_t)(g_off[g_te1[t]] + g_tp1[t]) * DM + c4;
    float4 y0 = *(const float4*)(g_y + r0);
    float4 y1 = *(const float4*)(g_y + r1);
    float4 o;
    o.x = g0 * y0.x + g1 * y1.x;
    o.y = g0 * y0.y + g1 * y1.y;
    o.z = g0 * y0.z + g1 * y1.z;
    o.w = g0 * y0.w + g1 * y1.w;
    *(float4*)(out + (size_t)idx * 4) = o;
}

// ---------------------------------------------------------------------------
extern "C" void kernel_launch(void* const* d_in, const int* in_sizes, int n_in,
                              void* d_out, int out_size) {
    const float* x  = (const float*)d_in[0];
    const float* rw = (const float*)d_in[1];
    const float* rb = (const float*)d_in[2];
    const float* w1 = (const float*)d_in[3];
    const float* b1 = (const float*)d_in[4];
    const float* w2 = (const float*)d_in[5];
    const float* b2 = (const float*)d_in[6];
    float* out = (float*)d_out;

    __half *xh, *w1h, *w2h;
    cudaGetSymbolAddress((void**)&xh,  g_xh);
    cudaGetSymbolAddress((void**)&w1h, g_w1h);
    cudaGetSymbolAddress((void**)&w2h, g_w2h);

    cudaFuncSetAttribute(moe_gemm<0>, cudaFuncAttributeMaxDynamicSharedMemorySize, GEMM_SMEM);
    cudaFuncSetAttribute(moe_gemm<1>, cudaFuncAttributeMaxDynamicSharedMemorySize, GEMM_SMEM);

    init_kernel<<<1, 32>>>();
    f2h_kernel<<<512, 256>>>(x,  xh,  T_TOK * DM / 8);
    f2h_kernel<<<2048, 256>>>(w1, w1h, NE * DM * DFF / 8);
    f2h_kernel<<<2048, 256>>>(w2, w2h, NE * DFF * DM / 8);
    router_kernel<<<512, 256>>>(x, rw, rb);
    prefix_kernel<<<1, 32>>>();
    moe_gemm<0><<<dim3(DFF / 128, MAXTILE - 8), 256, GEMM_SMEM>>>(w1h, b1);
    moe_gemm<1><<<dim3(DM  / 128, MAXTILE - 8), 256, GEMM_SMEM>>>(w2h, b2);
    mix_kernel<<<T_TOK * DM / 4 / 256, 256>>>(out);
}